// round 1
// baseline (speedup 1.0000x reference)
#include <cuda_runtime.h>

// Problem constants
#define LL 8
#define KK 8
#define NN 1048576
#define NVEC (NN / 4)          // 262144 float4 per (l,k) row
#define NPAIR 36               // triangular 8x8

// Scratch (allocation-free rule: __device__ globals)
__device__ float g_logits[LL * KK * KK];   // 512 floats
__device__ float g_W[LL * KK * KK];        // 512 floats

// ---------------------------------------------------------------------------
// Kernel 0: zero the logits accumulator (runs every replay)
// ---------------------------------------------------------------------------
__global__ void zero_logits_kernel() {
    int t = threadIdx.x;
    if (t < LL * KK * KK) g_logits[t] = 0.0f;
}

// ---------------------------------------------------------------------------
// Kernel 1: Gram matrices. grid = (BLKS_PER_L, L), block = 256
// Each thread: strided float4 loop; 8 coalesced row loads per n4;
// 36 triangular accumulators in registers.
// ---------------------------------------------------------------------------
__global__ void gram_kernel(const float* __restrict__ deltas) {
    const int l = blockIdx.y;
    const float4* __restrict__ base =
        reinterpret_cast<const float4*>(deltas) + (size_t)l * KK * NVEC;

    float acc[NPAIR];
#pragma unroll
    for (int p = 0; p < NPAIR; ++p) acc[p] = 0.0f;

    const int stride = gridDim.x * blockDim.x;
    for (int i = blockIdx.x * blockDim.x + threadIdx.x; i < NVEC; i += stride) {
        float4 v[KK];
#pragma unroll
        for (int j = 0; j < KK; ++j) v[j] = base[(size_t)j * NVEC + i];
        int p = 0;
#pragma unroll
        for (int a = 0; a < KK; ++a) {
#pragma unroll
            for (int b = a; b < KK; ++b) {
                acc[p] = fmaf(v[a].x, v[b].x, acc[p]);
                acc[p] = fmaf(v[a].y, v[b].y, acc[p]);
                acc[p] = fmaf(v[a].z, v[b].z, acc[p]);
                acc[p] = fmaf(v[a].w, v[b].w, acc[p]);
                ++p;
            }
        }
    }

    // warp reduce each accumulator
    __shared__ float sred[8][NPAIR];
    const int lane = threadIdx.x & 31;
    const int wid  = threadIdx.x >> 5;
#pragma unroll
    for (int p = 0; p < NPAIR; ++p) {
        float v = acc[p];
#pragma unroll
        for (int o = 16; o > 0; o >>= 1) v += __shfl_down_sync(0xffffffffu, v, o);
        if (lane == 0) sred[wid][p] = v;
    }
    __syncthreads();

    if (threadIdx.x < NPAIR) {
        float s = 0.0f;
#pragma unroll
        for (int w = 0; w < 8; ++w) s += sred[w][threadIdx.x];
        // map triangular index -> (a,b)
        int a = 0, rem = threadIdx.x;
        while (rem >= KK - a) { rem -= KK - a; ++a; }
        int b = a + rem;
        atomicAdd(&g_logits[l * KK * KK + a * KK + b], s);
        if (a != b) atomicAdd(&g_logits[l * KK * KK + b * KK + a], s);
    }
}

// ---------------------------------------------------------------------------
// Kernel 2: softmax + build W = I + clip(beta,0,1) * attn.   <<<1, 64>>>
// ---------------------------------------------------------------------------
__global__ void softmax_kernel(const float* __restrict__ beta) {
    int t = threadIdx.x;
    if (t >= LL * KK) return;
    int l = t >> 3, k = t & 7;
    const float scale = rsqrtf((float)NN);

    float v[KK];
    float m = -1e30f;
#pragma unroll
    for (int j = 0; j < KK; ++j) {
        v[j] = g_logits[l * KK * KK + k * KK + j] * scale;
        m = fmaxf(m, v[j]);
    }
    float s = 0.0f;
#pragma unroll
    for (int j = 0; j < KK; ++j) {
        v[j] = __expf(v[j] - m);
        s += v[j];
    }
    float inv = 1.0f / s;
    float b = fminf(fmaxf(beta[l * KK + k], 0.0f), 1.0f);
#pragma unroll
    for (int j = 0; j < KK; ++j) {
        float w = b * v[j] * inv + ((j == k) ? 1.0f : 0.0f);
        g_W[l * KK * KK + k * KK + j] = w;
    }
}

// ---------------------------------------------------------------------------
// Kernel 3: out[l,k,:] = last[l,k,:] + sum_j W[l,k,j] * deltas[l,j,:]
// grid = (BLKS_PER_L2, L), block = 256.  deltas[l,:,n4] loaded ONCE per n4,
// reused for all 8 k-outputs (register-level reuse, no redundant DRAM reads).
// ---------------------------------------------------------------------------
__global__ void apply_kernel(const float* __restrict__ last,
                             const float* __restrict__ deltas,
                             float* __restrict__ out) {
    const int l = blockIdx.y;
    __shared__ float W[KK * KK];
    if (threadIdx.x < KK * KK) W[threadIdx.x] = g_W[l * KK * KK + threadIdx.x];
    __syncthreads();

    const float4* __restrict__ d4 =
        reinterpret_cast<const float4*>(deltas) + (size_t)l * KK * NVEC;
    const float4* __restrict__ p4 =
        reinterpret_cast<const float4*>(last) + (size_t)l * KK * NVEC;
    float4* __restrict__ o4 =
        reinterpret_cast<float4*>(out) + (size_t)l * KK * NVEC;

    const int stride = gridDim.x * blockDim.x;
    for (int i = blockIdx.x * blockDim.x + threadIdx.x; i < NVEC; i += stride) {
        float4 v[KK];
#pragma unroll
        for (int j = 0; j < KK; ++j) v[j] = d4[(size_t)j * NVEC + i];
#pragma unroll
        for (int k = 0; k < KK; ++k) {
            float4 acc = p4[(size_t)k * NVEC + i];
#pragma unroll
            for (int j = 0; j < KK; ++j) {
                float w = W[k * KK + j];
                acc.x = fmaf(w, v[j].x, acc.x);
                acc.y = fmaf(w, v[j].y, acc.y);
                acc.z = fmaf(w, v[j].z, acc.z);
                acc.w = fmaf(w, v[j].w, acc.w);
            }
            o4[(size_t)k * NVEC + i] = acc;
        }
    }
}

// ---------------------------------------------------------------------------
extern "C" void kernel_launch(void* const* d_in, const int* in_sizes, int n_in,
                              void* d_out, int out_size) {
    const float* last_params = (const float*)d_in[0];
    const float* deltas      = (const float*)d_in[1];
    const float* beta        = (const float*)d_in[2];
    float* out               = (float*)d_out;

    zero_logits_kernel<<<1, 512>>>();
    gram_kernel<<<dim3(128, LL), 256>>>(deltas);
    softmax_kernel<<<1, 64>>>(beta);
    apply_kernel<<<dim3(256, LL), 256>>>(last_params, deltas, out);
}